// round 16
// baseline (speedup 1.0000x reference)
#include <cuda_runtime.h>
#include <cuda_bf16.h>

#define BB 512
#define SS 512
#define CC 96
#define NB 8                    // batches per CTA
#define FWD_T 64                // 2 forward warps (one team)
#define ALL_T 128               // + 2 numerator warps
#define SUP 144                 // u row stride (bf16)
#define SEP 108                 // em row pad (f32), 16B multiple
#define RING 8

__device__ float g_num[BB];
__device__ float g_den[BB];

__device__ __forceinline__ float fast_rcp(float x) {
    float r;
    asm("rcp.approx.f32 %0, %1;" : "=f"(r) : "f"(x));
    return r;
}
__device__ __forceinline__ unsigned pack_bf16(float x, float y) {
    __nv_bfloat162 h = __floats2bfloat162_rn(x, y);
    return *reinterpret_cast<unsigned*>(&h);
}
__device__ __forceinline__ void mma_bf16(
    float& d0, float& d1, float& d2, float& d3,
    unsigned a0, unsigned a1, unsigned a2, unsigned a3,
    unsigned b0, unsigned b1)
{
    asm volatile(
        "mma.sync.aligned.m16n8k16.row.col.f32.bf16.bf16.f32 "
        "{%0,%1,%2,%3},{%4,%5,%6,%7},{%8,%9},{%0,%1,%2,%3};"
        : "+f"(d0), "+f"(d1), "+f"(d2), "+f"(d3)
        : "r"(a0), "r"(a1), "r"(a2), "r"(a3), "r"(b0), "r"(b1));
}
__device__ __forceinline__ void cp_async16(void* dst, const void* src) {
    unsigned d = (unsigned)__cvta_generic_to_shared(dst);
    asm volatile("cp.async.cg.shared.global [%0], [%1], 16;" :: "r"(d), "l"(src));
}
__device__ __forceinline__ void cp_async4(void* dst, const void* src) {
    unsigned d = (unsigned)__cvta_generic_to_shared(dst);
    asm volatile("cp.async.ca.shared.global [%0], [%1], 4;" :: "r"(d), "l"(src));
}
#define CP_COMMIT() asm volatile("cp.async.commit_group;" ::: "memory")
#define CP_WAIT4()  asm volatile("cp.async.wait_group 4;" ::: "memory")
#define FBAR()      asm volatile("bar.sync 1, %0;" :: "r"(FWD_T) : "memory")

__device__ __forceinline__ int perm96(int s) {
    int base = s & ~15, r = s & 15, hi = r >> 3, low = r & 7;
    return base + 4 * (low >> 1) + 2 * hi + (low & 1);
}

// =====================================================================
// Fused forward + numerator. 64 CTAs x 128 threads.
// Threads 0..63: 2-warp tensor-core forward team (warp w owns M-tiles
// {3w..3w+2}); named barrier 1 (64 threads), one per step.
// Stale normalizer: iter t uses r = rcp(u(t-2)[0]) from a 4-slot ring;
// exact shift S -= log(r_applied). Depth-8 cp.async ring (wait_group 4)
// guarantees em/mask buffer t+2 before iter t starts.
// Threads 64..127: numerator warps, free-running.
// =====================================================================
__global__ __launch_bounds__(ALL_T, 1) void crf_fused_kernel(
    const float* __restrict__ em,
    const int* __restrict__ tags,
    const int* __restrict__ masks,
    const float* __restrict__ start,
    const float* __restrict__ endt,
    const float* __restrict__ trans)
{
    __shared__ __align__(16) __nv_bfloat16 s_u[2][NB][SUP];
    __shared__ __align__(16) float s_em[RING][NB * SEP];
    __shared__ float s_r[4][NB];
    __shared__ int   s_mk[RING][NB];
    __shared__ float s_ee[CC];
    __shared__ float s_S[NB];

    const int tid = threadIdx.x;
    const int b0g = blockIdx.x * NB;

    // ================= numerator warps =================
    if (tid >= FWD_T) {
        const int w2 = (tid - FWD_T) >> 5;
        const int lane = tid & 31;
#pragma unroll
        for (int k = 0; k < 4; k++) {
            const int b = b0g + w2 * 4 + k;
            const int* tg = tags + (size_t)b * SS;
            const int* mk = masks + (size_t)b * SS;
            const float* e = em + (size_t)b * SS * CC;
            float s = 0.f;
            int cnt = 0;
            for (int t = lane; t < SS; t += 32) {
                int tagt = tg[t];
                int m = mk[t];
                cnt += m ? 1 : 0;
                if (t == 0) {
                    s += start[tagt] + e[tagt];
                } else if (m) {
                    int tp = tg[t - 1];
                    s += trans[tp * CC + tagt] + e[(size_t)t * CC + tagt];
                }
            }
#pragma unroll
            for (int o = 16; o; o >>= 1) {
                s += __shfl_xor_sync(0xFFFFFFFFu, s, o);
                cnt += __shfl_xor_sync(0xFFFFFFFFu, cnt, o);
            }
            if (lane == 0) g_num[b] = s + endt[tg[cnt - 1]];
        }
        return;
    }

    // ================= forward team (2 warps) =================
    const int w    = tid >> 5;          // team warp 0..1 -> M-tiles 3w..3w+2
    const int lane = tid & 31;
    const int lr   = lane >> 2;
    const int lc   = lane & 3;
    const int n0 = 2 * lc, n1 = n0 + 1;
    const bool owner0 = (w == 0) && (lr == 0);   // state-0 owner lanes

    // A fragments for my 3 M-tiles (verified R13 mapping)
    unsigned A[3][6][4];
    int S0i[3], S1i[3], P0i[3], P1i[3];
#pragma unroll
    for (int m = 0; m < 3; m++) {
        int mtg = 3 * w + m;
        int s0 = 16 * mtg + lr, s1 = s0 + 8;
        S0i[m] = s0; S1i[m] = s1;
        P0i[m] = 16 * mtg + 4 * (lr >> 1) + (lr & 1);
        P1i[m] = P0i[m] + 2;
#pragma unroll
        for (int kt = 0; kt < 6; kt++) {
            int k0 = 16 * kt + 2 * lc;
            A[m][kt][0] = pack_bf16(__expf(trans[(k0 + 0) * CC + s0]), __expf(trans[(k0 + 1) * CC + s0]));
            A[m][kt][1] = pack_bf16(__expf(trans[(k0 + 0) * CC + s1]), __expf(trans[(k0 + 1) * CC + s1]));
            A[m][kt][2] = pack_bf16(__expf(trans[(k0 + 8) * CC + s0]), __expf(trans[(k0 + 9) * CC + s0]));
            A[m][kt][3] = pack_bf16(__expf(trans[(k0 + 8) * CC + s1]), __expf(trans[(k0 + 9) * CC + s1]));
        }
    }

    // t = 0 state: 12 cells per lane
    float u[3][4];
#pragma unroll
    for (int m = 0; m < 3; m++) {
        u[m][0] = __expf(start[S0i[m]] + em[(size_t)(b0g + n0) * SS * CC + S0i[m]]);
        u[m][1] = __expf(start[S0i[m]] + em[(size_t)(b0g + n1) * SS * CC + S0i[m]]);
        u[m][2] = __expf(start[S1i[m]] + em[(size_t)(b0g + n0) * SS * CC + S1i[m]]);
        u[m][3] = __expf(start[S1i[m]] + em[(size_t)(b0g + n1) * SS * CC + S1i[m]]);
        s_u[0][n0][P0i[m]] = __float2bfloat16(u[m][0]);
        s_u[0][n1][P0i[m]] = __float2bfloat16(u[m][1]);
        s_u[0][n0][P1i[m]] = __float2bfloat16(u[m][2]);
        s_u[0][n1][P1i[m]] = __float2bfloat16(u[m][3]);
    }
    float Sa = 0.f, Sb = 0.f;
    if (owner0) {
        float r0i = fast_rcp(u[0][0]);
        float r1i = fast_rcp(u[0][1]);
        s_r[1][n0] = r0i; s_r[2][n0] = r0i;
        s_r[1][n1] = r1i; s_r[2][n1] = r1i;
    }
    for (int j = tid; j < CC; j += FWD_T) s_ee[perm96(j)] = __expf(endt[j]);

    // E for t = 1 directly from global
    float E[3][4];
#pragma unroll
    for (int m = 0; m < 3; m++) {
        E[m][0] = __expf(em[(size_t)(b0g + n0) * SS * CC + CC + S0i[m]]);
        E[m][1] = __expf(em[(size_t)(b0g + n1) * SS * CC + CC + S0i[m]]);
        E[m][2] = __expf(em[(size_t)(b0g + n0) * SS * CC + CC + S1i[m]]);
        E[m][3] = __expf(em[(size_t)(b0g + n1) * SS * CC + CC + S1i[m]]);
    }

    // cp.async prologue: stage em/mask for t = 1..7 (3 chunks/thread)
#pragma unroll
    for (int tt = 1; tt <= 7; tt++) {
#pragma unroll
        for (int c = 0; c < 3; c++) {
            int id = tid + FWD_T * c;          // 0..191
            int rn = id / 24, off = (id % 24) * 4;
            cp_async16(&s_em[tt][rn * SEP + off],
                       em + (size_t)(b0g + rn) * SS * CC + (size_t)tt * CC + off);
        }
        if (tid < NB) cp_async4(&s_mk[tt][tid], masks + (size_t)(b0g + tid) * SS + tt);
        CP_COMMIT();
    }
    CP_WAIT4();      // buffers 1..3 complete
    FBAR();

    int p = 0;
    for (int t = 1; t < SS; t++) {
        // prefetch t+7
        int tp = t + 7;
        if (tp < SS) {
#pragma unroll
            for (int c = 0; c < 3; c++) {
                int id = tid + FWD_T * c;
                int rn = id / 24, off = (id % 24) * 4;
                cp_async16(&s_em[tp & 7][rn * SEP + off],
                           em + (size_t)(b0g + rn) * SS * CC + (size_t)tp * CC + off);
            }
            if (tid < NB) cp_async4(&s_mk[tp & 7][tid], masks + (size_t)(b0g + tid) * SS + tp);
        }
        CP_COMMIT();

        const int eb = t & 7;
        float r0 = s_r[t & 3][n0], r1 = s_r[t & 3][n1];
        int m0 = s_mk[eb][n0], m1 = s_mk[eb][n1];
        float er[3][4];
#pragma unroll
        for (int m = 0; m < 3; m++) {
            er[m][0] = E[m][0] * r0; er[m][1] = E[m][1] * r1;
            er[m][2] = E[m][2] * r0; er[m][3] = E[m][3] * r1;
        }
        float lg0 = 0.f, lg1 = 0.f;
        if (owner0) { lg0 = __logf(r0); lg1 = __logf(r1); }

        // B fragments: 6 LDS.64 (shared across my 3 M-tiles)
        uint2 bb[6];
#pragma unroll
        for (int kt = 0; kt < 6; kt++)
            bb[kt] = *(const uint2*)&s_u[p][lr][16 * kt + 4 * lc];

        // 6 independent 3-deep MMA chains (3 M-tiles x 2 accumulators)
        float d[3][4], e2[3][4];
#pragma unroll
        for (int m = 0; m < 3; m++) {
            d[m][0] = d[m][1] = d[m][2] = d[m][3] = 0.f;
            e2[m][0] = e2[m][1] = e2[m][2] = e2[m][3] = 0.f;
        }
#pragma unroll
        for (int kt = 0; kt < 3; kt++) {
#pragma unroll
            for (int m = 0; m < 3; m++) {
                mma_bf16(d[m][0], d[m][1], d[m][2], d[m][3],
                         A[m][2 * kt][0], A[m][2 * kt][1], A[m][2 * kt][2], A[m][2 * kt][3],
                         bb[2 * kt].x, bb[2 * kt].y);
                mma_bf16(e2[m][0], e2[m][1], e2[m][2], e2[m][3],
                         A[m][2 * kt + 1][0], A[m][2 * kt + 1][1], A[m][2 * kt + 1][2], A[m][2 * kt + 1][3],
                         bb[2 * kt + 1].x, bb[2 * kt + 1].y);
            }
        }

        // E for t+1 under MMA shadow (buffer t+1 guaranteed complete)
        const int en = (t + 1) & 7;
        float nE[3][4];
#pragma unroll
        for (int m = 0; m < 3; m++) {
            nE[m][0] = __expf(s_em[en][n0 * SEP + S0i[m]]);
            nE[m][1] = __expf(s_em[en][n1 * SEP + S0i[m]]);
            nE[m][2] = __expf(s_em[en][n0 * SEP + S1i[m]]);
            nE[m][3] = __expf(s_em[en][n1 * SEP + S1i[m]]);
        }

        // epilogue: u_new = (d+e)*E*r, masked; store permuted bf16
#pragma unroll
        for (int m = 0; m < 3; m++) {
            float v0 = (d[m][0] + e2[m][0]) * er[m][0];
            float v1 = (d[m][1] + e2[m][1]) * er[m][1];
            float v2 = (d[m][2] + e2[m][2]) * er[m][2];
            float v3 = (d[m][3] + e2[m][3]) * er[m][3];
            u[m][0] = m0 ? v0 : u[m][0];
            u[m][1] = m1 ? v1 : u[m][1];
            u[m][2] = m0 ? v2 : u[m][2];
            u[m][3] = m1 ? v3 : u[m][3];
            s_u[p ^ 1][n0][P0i[m]] = __float2bfloat16(u[m][0]);
            s_u[p ^ 1][n1][P0i[m]] = __float2bfloat16(u[m][1]);
            s_u[p ^ 1][n0][P1i[m]] = __float2bfloat16(u[m][2]);
            s_u[p ^ 1][n1][P1i[m]] = __float2bfloat16(u[m][3]);
        }
        if (owner0) {
            // normalizer for step t+2 (off critical path) + exact shift
            s_r[(t + 2) & 3][n0] = fast_rcp(u[0][0]);
            s_r[(t + 2) & 3][n1] = fast_rcp(u[0][1]);
            Sa = m0 ? Sa - lg0 : Sa;
            Sb = m1 ? Sb - lg1 : Sb;
        }
#pragma unroll
        for (int m = 0; m < 3; m++) {
            E[m][0] = nE[m][0]; E[m][1] = nE[m][1];
            E[m][2] = nE[m][2]; E[m][3] = nE[m][3];
        }

        CP_WAIT4();
        FBAR();
        p ^= 1;
    }

    if (owner0) { s_S[n0] = Sa; s_S[n1] = Sb; }
    FBAR();
    if (tid < NB) {
        float s = 0.f;
        for (int j = 0; j < CC; j++)
            s += __bfloat162float(s_u[p][tid][j]) * s_ee[j];
        g_den[b0g + tid] = s_S[tid] + __logf(s);
    }
}

// =====================================================================
// Final mean reduce
// =====================================================================
__global__ void crf_reduce_kernel(float* __restrict__ out)
{
    __shared__ float sh[BB];
    int t = threadIdx.x;
    sh[t] = g_num[t] - g_den[t];
    __syncthreads();
#pragma unroll
    for (int o = BB / 2; o > 0; o >>= 1) {
        if (t < o) sh[t] += sh[t + o];
        __syncthreads();
    }
    if (t == 0) out[0] = sh[0] * (1.0f / (float)BB);
}

extern "C" void kernel_launch(void* const* d_in, const int* in_sizes, int n_in,
                              void* d_out, int out_size)
{
    const float* em    = (const float*)d_in[0];
    const int*   tags  = (const int*)d_in[1];
    const int*   masks = (const int*)d_in[2];
    const float* start = (const float*)d_in[3];
    const float* endt  = (const float*)d_in[4];
    const float* trans = (const float*)d_in[5];
    float* out = (float*)d_out;

    crf_fused_kernel<<<BB / NB, ALL_T>>>(em, tags, masks, start, endt, trans);
    crf_reduce_kernel<<<1, BB>>>(out);
}